// round 3
// baseline (speedup 1.0000x reference)
#include <cuda_runtime.h>
#include <math.h>

#define BATCH 8
#define TQ 1024
#define TM 1024
#define DIM 512
#define ATTND 512
#define NH 8
#define HD 64
#define NEG_INF_F (-4294967295.0f)

// Scratch for projected Q/K/V (static __device__ arrays: allowed, no runtime alloc)
__device__ float g_Q[(size_t)BATCH * TQ * ATTND];
__device__ float g_K[(size_t)BATCH * TM * ATTND];
__device__ float g_V[(size_t)BATCH * TM * ATTND];

// ---------------------------------------------------------------------------
// SGEMM: C[M,512] = A[M,512] @ W[512,512], fp32, 128x128 tile, kt=8, 8x8 micro
// ---------------------------------------------------------------------------
__global__ __launch_bounds__(256) void sgemm_k512(
    const float* __restrict__ A, const float* __restrict__ W, float* __restrict__ C)
{
    __shared__ float As[8][128];
    __shared__ float Bs[8][128];

    const int t  = threadIdx.x;
    const int tx = t & 15;        // 16 col groups (8 cols each)
    const int ty = t >> 4;        // 16 row groups (8 rows each)
    const int m0 = blockIdx.y * 128;
    const int n0 = blockIdx.x * 128;

    const int lrow = t >> 1, lseg = t & 1;   // A loader: 128 rows x 2 float4
    const int lkk  = t >> 5, lsg  = t & 31;  // W loader: 8 k-rows x 32 float4

    float acc[8][8];
#pragma unroll
    for (int i = 0; i < 8; i++)
#pragma unroll
        for (int j = 0; j < 8; j++) acc[i][j] = 0.f;

    for (int k0 = 0; k0 < 512; k0 += 8) {
        float4 av = *(const float4*)&A[(size_t)(m0 + lrow) * 512 + k0 + lseg * 4];
        As[lseg * 4 + 0][lrow] = av.x;
        As[lseg * 4 + 1][lrow] = av.y;
        As[lseg * 4 + 2][lrow] = av.z;
        As[lseg * 4 + 3][lrow] = av.w;
        *(float4*)&Bs[lkk][lsg * 4] =
            *(const float4*)&W[(size_t)(k0 + lkk) * 512 + n0 + lsg * 4];
        __syncthreads();
#pragma unroll
        for (int kk = 0; kk < 8; kk++) {
            float a[8], bb[8];
#pragma unroll
            for (int i = 0; i < 8; i++) a[i] = As[kk][ty * 8 + i];
            float4 b0 = *(float4*)&Bs[kk][tx * 8];
            float4 b1 = *(float4*)&Bs[kk][tx * 8 + 4];
            bb[0] = b0.x; bb[1] = b0.y; bb[2] = b0.z; bb[3] = b0.w;
            bb[4] = b1.x; bb[5] = b1.y; bb[6] = b1.z; bb[7] = b1.w;
#pragma unroll
            for (int i = 0; i < 8; i++)
#pragma unroll
                for (int j = 0; j < 8; j++) acc[i][j] = fmaf(a[i], bb[j], acc[i][j]);
        }
        __syncthreads();
    }
#pragma unroll
    for (int i = 0; i < 8; i++) {
        float* crow = &C[(size_t)(m0 + ty * 8 + i) * 512 + n0 + tx * 8];
        *(float4*)&crow[0] = make_float4(acc[i][0], acc[i][1], acc[i][2], acc[i][3]);
        *(float4*)&crow[4] = make_float4(acc[i][4], acc[i][5], acc[i][6], acc[i][7]);
    }
}

// ---------------------------------------------------------------------------
// Fused attention per (b, h, 128-query tile):
//  phase 1: S = Q K^T * 0.125, mask (causal + lengths), online max/sum, raw S -> align
//  reduce : 16-lane shfl flash merge -> rowmax, 1/rowsum in smem
//  phase 3: P = exp(S-max)/sum (re-read S from L2), write P to align, ctx = P @ V
// ---------------------------------------------------------------------------
#define QS_STRIDE 65     // Qs/Ps row stride  (128 rows)
#define KT_STRIDE 132    // Kts row stride    (64 d rows x 128 keys)
#define VS_STRIDE 68     // Vs row stride     (64 m rows x 64 dims)

__global__ __launch_bounds__(256) void attn_kernel(
    const int* __restrict__ mem_len, const int* __restrict__ qry_len,
    float* __restrict__ ctx_out, float* __restrict__ align_out)
{
    extern __shared__ float sm[];
    float* Qs   = sm;                         // [128][65]  (reused as Ps)
    float* Kts  = sm + 128 * QS_STRIDE;       // [64][132]  (reused as Vs[64][68])
    float* rmax = Kts + 64 * KT_STRIDE;       // [128]
    float* rinv = rmax + 128;                 // [128]

    const int t  = threadIdx.x;
    const int tx = t & 15;
    const int ty = t >> 4;
    const int q0 = blockIdx.x * 128;
    const int h  = blockIdx.y;
    const int b  = blockIdx.z;

    const int mlen = mem_len[b];
    const int qlen = qry_len[b];

    const float* Qbase = g_Q + (size_t)b * TQ * ATTND + h * HD;
    const float* Kbase = g_K + (size_t)b * TM * ATTND + h * HD;
    const float* Vbase = g_V + (size_t)b * TM * ATTND + h * HD;
    float* arow = align_out + ((size_t)(b * NH + h)) * TQ * TM;

    // ---- load Q tile (128 x 64) ----
#pragma unroll
    for (int it = 0; it < 8; it++) {
        int idx = t + it * 256;             // 0..2047 float4s
        int r = idx >> 4, seg = idx & 15;
        float4 v = *(const float4*)&Qbase[(size_t)(q0 + r) * ATTND + seg * 4];
        float* dst = &Qs[r * QS_STRIDE + seg * 4];
        dst[0] = v.x; dst[1] = v.y; dst[2] = v.z; dst[3] = v.w;
    }

    float rm[8], rl[8];
#pragma unroll
    for (int i = 0; i < 8; i++) { rm[i] = -INFINITY; rl[i] = 0.f; }

    // ---- phase 1: logits over key tiles of 128 ----
    for (int k0 = 0; k0 < TM; k0 += 128) {
        __syncthreads();   // protect Kts reuse / Qs first use
        // load K tile transposed: Kts[d][key]
#pragma unroll
        for (int it = 0; it < 8; it++) {
            int idx = t + it * 256;
            int key = idx >> 4, seg = idx & 15;
            float4 v = *(const float4*)&Kbase[(size_t)(k0 + key) * ATTND + seg * 4];
            Kts[(seg * 4 + 0) * KT_STRIDE + key] = v.x;
            Kts[(seg * 4 + 1) * KT_STRIDE + key] = v.y;
            Kts[(seg * 4 + 2) * KT_STRIDE + key] = v.z;
            Kts[(seg * 4 + 3) * KT_STRIDE + key] = v.w;
        }
        __syncthreads();

        float s[8][8];
#pragma unroll
        for (int i = 0; i < 8; i++)
#pragma unroll
            for (int j = 0; j < 8; j++) s[i][j] = 0.f;

#pragma unroll
        for (int kk = 0; kk < 64; kk++) {
            float a[8], bb[8];
#pragma unroll
            for (int i = 0; i < 8; i++) a[i] = Qs[(ty * 8 + i) * QS_STRIDE + kk];
            float4 b0 = *(float4*)&Kts[kk * KT_STRIDE + tx * 8];
            float4 b1 = *(float4*)&Kts[kk * KT_STRIDE + tx * 8 + 4];
            bb[0] = b0.x; bb[1] = b0.y; bb[2] = b0.z; bb[3] = b0.w;
            bb[4] = b1.x; bb[5] = b1.y; bb[6] = b1.z; bb[7] = b1.w;
#pragma unroll
            for (int i = 0; i < 8; i++)
#pragma unroll
                for (int j = 0; j < 8; j++) s[i][j] = fmaf(a[i], bb[j], s[i][j]);
        }

        // mask + scale + store raw logits + online softmax state
#pragma unroll
        for (int i = 0; i < 8; i++) {
            const int q = q0 + ty * 8 + i;
            const bool qv = q < qlen;
            float vals[8];
#pragma unroll
            for (int j = 0; j < 8; j++) {
                int m = k0 + tx * 8 + j;
                bool ok = qv && (m <= q) && (m < mlen);
                vals[j] = ok ? s[i][j] * 0.125f : NEG_INF_F;
            }
            float* dst = &arow[(size_t)q * TM + k0 + tx * 8];
            *(float4*)&dst[0] = make_float4(vals[0], vals[1], vals[2], vals[3]);
            *(float4*)&dst[4] = make_float4(vals[4], vals[5], vals[6], vals[7]);

            float tmx = vals[0];
#pragma unroll
            for (int j = 1; j < 8; j++) tmx = fmaxf(tmx, vals[j]);
            float tsum = 0.f;
#pragma unroll
            for (int j = 0; j < 8; j++) tsum += __expf(vals[j] - tmx);
            float nm = fmaxf(rm[i], tmx);
            rl[i] = rl[i] * __expf(rm[i] - nm) + tsum * __expf(tmx - nm);
            rm[i] = nm;
        }
    }

    // ---- cross-tx flash merge (16 lanes per row group) ----
#pragma unroll
    for (int i = 0; i < 8; i++) {
        float m_ = rm[i], l_ = rl[i];
#pragma unroll
        for (int off = 8; off >= 1; off >>= 1) {
            float om = __shfl_xor_sync(0xffffffffu, m_, off, 16);
            float ol = __shfl_xor_sync(0xffffffffu, l_, off, 16);
            float nm = fmaxf(m_, om);
            l_ = l_ * __expf(m_ - nm) + ol * __expf(om - nm);
            m_ = nm;
        }
        if (tx == 0) {
            rmax[ty * 8 + i] = m_;
            rinv[ty * 8 + i] = 1.0f / l_;
        }
    }

    // ---- phase 3: normalized P (write back) + ctx = P @ V ----
    float* Ps = Qs;     // [128][65]
    float* Vs = Kts;    // [64][68]
    float ctx[8][4];
#pragma unroll
    for (int i = 0; i < 8; i++)
#pragma unroll
        for (int j = 0; j < 4; j++) ctx[i][j] = 0.f;

    for (int m0 = 0; m0 < TM; m0 += 64) {
        __syncthreads();   // buffers reuse + rmax/rinv visibility on first iter
        // load V tile [64][64]
#pragma unroll
        for (int it = 0; it < 4; it++) {
            int idx = t + it * 256;           // 0..1023 float4s
            int m = idx >> 4, seg = idx & 15;
            float4 v = *(const float4*)&Vbase[(size_t)(m0 + m) * ATTND + seg * 4];
            float* dst = &Vs[m * VS_STRIDE + seg * 4];
            dst[0] = v.x; dst[1] = v.y; dst[2] = v.z; dst[3] = v.w;
        }
        // compute P tile, write normalized probs back to align
#pragma unroll
        for (int n = 0; n < 32; n++) {
            int e = t + n * 256;              // 0..8191
            int r = e >> 6, m = e & 63;
            size_t gi = (size_t)(q0 + r) * TM + m0 + m;
            float sval = arow[gi];
            float p = __expf(sval - rmax[r]) * rinv[r];
            arow[gi] = p;
            Ps[r * QS_STRIDE + m] = p;
        }
        __syncthreads();
        // micro GEMM: ctx[128][64] += Ps[128][64] @ Vs[64][64]
#pragma unroll
        for (int m = 0; m < 64; m++) {
            float a[8];
#pragma unroll
            for (int i = 0; i < 8; i++) a[i] = Ps[(ty * 8 + i) * QS_STRIDE + m];
            float4 bv = *(float4*)&Vs[m * VS_STRIDE + tx * 4];
#pragma unroll
            for (int i = 0; i < 8; i++) {
                ctx[i][0] = fmaf(a[i], bv.x, ctx[i][0]);
                ctx[i][1] = fmaf(a[i], bv.y, ctx[i][1]);
                ctx[i][2] = fmaf(a[i], bv.z, ctx[i][2]);
                ctx[i][3] = fmaf(a[i], bv.w, ctx[i][3]);
            }
        }
    }

    // write contexts: (b, q, h*64 + d)
#pragma unroll
    for (int i = 0; i < 8; i++) {
        size_t off = (size_t)(b * TQ + q0 + ty * 8 + i) * ATTND + h * HD + tx * 4;
        *(float4*)&ctx_out[off] = make_float4(ctx[i][0], ctx[i][1], ctx[i][2], ctx[i][3]);
    }
}

// ---------------------------------------------------------------------------
extern "C" void kernel_launch(void* const* d_in, const int* in_sizes, int n_in,
                              void* d_out, int out_size)
{
    const float* inputs = (const float*)d_in[0];
    const float* memory = (const float*)d_in[1];
    const float* Wq     = (const float*)d_in[2];
    const float* Wk     = (const float*)d_in[3];
    const float* Wv     = (const float*)d_in[4];
    const int*   mlen   = (const int*)d_in[5];
    const int*   qlen   = (const int*)d_in[6];

    float* out   = (float*)d_out;
    float* ctx   = out;                                   // (B, TQ, ATTN)
    float* align = out + (size_t)BATCH * TQ * ATTND;      // (B, H, TQ, TM)

    float *Qb, *Kb, *Vb;
    cudaGetSymbolAddress((void**)&Qb, g_Q);
    cudaGetSymbolAddress((void**)&Kb, g_K);
    cudaGetSymbolAddress((void**)&Vb, g_V);

    // QKV projections: M = B*T = 8192
    dim3 ggrid(4, 64);
    sgemm_k512<<<ggrid, 256>>>(inputs, Wq, Qb);
    sgemm_k512<<<ggrid, 256>>>(memory, Wk, Kb);
    sgemm_k512<<<ggrid, 256>>>(memory, Wv, Vb);

    // fused attention
    const int smem_bytes = (128 * QS_STRIDE + 64 * KT_STRIDE + 256) * sizeof(float);
    cudaFuncSetAttribute(attn_kernel, cudaFuncAttributeMaxDynamicSharedMemorySize,
                         smem_bytes);
    dim3 agrid(TQ / 128, NH, BATCH);
    attn_kernel<<<agrid, 256, smem_bytes>>>(mlen, qlen, ctx, align);
}